// round 1
// baseline (speedup 1.0000x reference)
#include <cuda_runtime.h>

// Lorenz96 correction: conv1(1->72,k5,wrap)+gate -> 48ch, conv2(48->37,k5,wrap),
// conv3(1x1) + 18-term quadratic stencil head. B=65536, X=40.

#define NT       320
#define S_PER_BLK 8
#define X        40
#define HS_CI    45                 // 44 halo cols + 1 pad
#define HS_S     (48*HS_CI + 8)     // 2168 floats per sample, %32 != 0

// SMEM float layout (all region sizes multiples of 4 floats):
//  coeffs[20] W1s[360] b1s[72] W2s[8880] b2s[40] W3s[40] b3s[4] us[360] hs[8*2168]
#define OFF_COEFF 0
#define OFF_W1    20
#define OFF_B1    (OFF_W1+360)
#define OFF_W2    (OFF_B1+72)
#define OFF_B2    (OFF_W2+8880)
#define OFF_W3    (OFF_B2+40)
#define OFF_B3    (OFF_W3+40)
#define OFF_US    (OFF_B3+4)
#define OFF_HS    (OFF_US+360)
#define SMEM_FLOATS (OFF_HS + S_PER_BLK*HS_S)   // 27120 floats = 108480 B

__global__ __launch_bounds__(NT, 2)
void l96_kernel(const float* __restrict__ u,  const float* __restrict__ coeff,
                const float* __restrict__ W1, const float* __restrict__ b1,
                const float* __restrict__ W2, const float* __restrict__ b2,
                const float* __restrict__ W3, const float* __restrict__ b3,
                float* __restrict__ out)
{
    extern __shared__ float sm[];
    float* coeffs = sm + OFF_COEFF;
    float* W1s    = sm + OFF_W1;
    float* b1s    = sm + OFF_B1;
    float* W2s    = sm + OFF_W2;   // layout [(ci*5+d)*37 + co]
    float* b2s    = sm + OFF_B2;
    float* W3s    = sm + OFF_W3;
    float* b3s    = sm + OFF_B3;
    float* us     = sm + OFF_US;   // [s][45] halo-padded u
    float* hs     = sm + OFF_HS;   // [s][48][45] halo-padded gated activations

    const int tid = threadIdx.x;
    const int blockBase = blockIdx.x * S_PER_BLK;

    // ---- stage weights ----
    for (int i = tid; i < 18;   i += NT) coeffs[i] = coeff[i];
    for (int i = tid; i < 360;  i += NT) W1s[i] = W1[i];
    for (int i = tid; i < 72;   i += NT) b1s[i] = b1[i];
    for (int i = tid; i < 8880; i += NT) {
        int co = i / 240, r = i % 240;       // r = ci*5 + d
        W2s[r * 37 + co] = W2[i];
    }
    for (int i = tid; i < 37; i += NT) { b2s[i] = b2[i]; W3s[i] = W3[i]; }
    if (tid == 0) b3s[0] = b3[0];

    // ---- stage u with wrap halo ----
    for (int i = tid; i < S_PER_BLK * X; i += NT) {
        int s = i / X, p = i % X;
        float v = u[(size_t)(blockBase + s) * X + p];
        float* ur = us + s * HS_CI;
        ur[p + 2] = v;
        if (p < 2)   ur[p + 42] = v;
        if (p >= 38) ur[p - 38] = v;
    }
    __syncthreads();

    // ---- conv1 + relu + gate -> hs (48 channels, halo-padded) ----
    for (int i = tid; i < S_PER_BLK * 48 * X; i += NT) {
        int p = i % X;
        int c = (i / X) % 48;
        int s = i / (48 * X);
        const float* up = us + s * HS_CI + p;   // up[d] = u[p + d - 2] (wrapped)
        float a = b1s[c];
        #pragma unroll
        for (int d = 0; d < 5; d++) a = fmaf(W1s[c * 5 + d], up[d], a);
        a = fmaxf(a, 0.f);
        if (c >= 24) {
            int c2 = c + 24;
            float g = b1s[c2];
            #pragma unroll
            for (int d = 0; d < 5; d++) g = fmaf(W1s[c2 * 5 + d], up[d], g);
            a *= fmaxf(g, 0.f);
        }
        float* hr = hs + s * HS_S + c * HS_CI;
        hr[p + 2] = a;
        if (p < 2)   hr[p + 42] = a;
        if (p >= 38) hr[p - 38] = a;
    }
    __syncthreads();

    // ---- conv2: thread = (sample, co), 40 position accumulators in regs ----
    const int s  = tid / X;        // 0..7
    const int co = tid % X;        // 0..39; active if < 37
    const bool active = (co < 37);

    float acc[40];
    if (active) {
        #pragma unroll
        for (int j = 0; j < 40; j++) acc[j] = b2s[co];

        const float* hbase = hs + s * HS_S;
        const float* wco   = W2s + co;
        #pragma unroll 1
        for (int ci = 0; ci < 48; ci++) {
            const float* hr = hbase + ci * HS_CI;
            const float* w  = wco + ci * 185;        // (ci*5+d)*37 + co
            float w0 = w[0], w1 = w[37], w2 = w[74], w3_ = w[111], w4 = w[148];
            float h0 = hr[0], h1 = hr[1], h2 = hr[2], h3 = hr[3];
            #pragma unroll
            for (int j = 0; j < 40; j++) {
                float h4 = hr[j + 4];
                float t = fmaf(w0, h0,
                          fmaf(w1, h1,
                          fmaf(w2, h2,
                          fmaf(w3_, h3, w4 * h4))));
                acc[j] += t;
                h0 = h1; h1 = h2; h2 = h3; h3 = h4;
            }
        }
        // relu + conv3 weight (per-channel scalar)
        float wc = W3s[co];
        #pragma unroll
        for (int j = 0; j < 40; j++) acc[j] = wc * fmaxf(acc[j], 0.f);
    }
    __syncthreads();   // all hs reads complete; safe to alias hs as partial buffer

    if (active) {
        float* rp = hs + (s * 37 + co) * 40;   // partials [s][co][p], 160B-aligned
        #pragma unroll
        for (int j = 0; j < 40; j += 4)
            *reinterpret_cast<float4*>(rp + j) =
                make_float4(acc[j], acc[j+1], acc[j+2], acc[j+3]);
    }
    __syncthreads();

    // ---- epilogue: stencil head + b3 + sum over co, thread = (s, p) ----
    {
        const int s2 = tid / X, p = tid % X;
        const float* ur = us + s2 * HS_CI + p;
        float um2 = ur[0], um1 = ur[1], uc = ur[2], up1 = ur[3], up2 = ur[4];
        float o = coeffs[0];
        o = fmaf(coeffs[1],  um2,        o);
        o = fmaf(coeffs[2],  um1,        o);
        o = fmaf(coeffs[3],  uc,         o);
        o = fmaf(coeffs[4],  up1,        o);
        o = fmaf(coeffs[5],  up2,        o);
        o = fmaf(coeffs[6],  um2 * um2,  o);
        o = fmaf(coeffs[7],  um1 * um1,  o);
        o = fmaf(coeffs[8],  uc  * uc,   o);
        o = fmaf(coeffs[9],  up1 * up1,  o);
        o = fmaf(coeffs[10], up2 * up2,  o);
        o = fmaf(coeffs[11], um2 * um1,  o);
        o = fmaf(coeffs[12], um1 * uc,   o);
        o = fmaf(coeffs[13], uc  * up1,  o);
        o = fmaf(coeffs[14], up1 * up2,  o);
        o = fmaf(coeffs[15], um2 * uc,   o);
        o = fmaf(coeffs[16], um1 * up1,  o);
        o = fmaf(coeffs[17], uc  * up2,  o);
        o += b3s[0];

        const float* rpb = hs + s2 * 37 * 40 + p;
        #pragma unroll 1
        for (int c2 = 0; c2 < 37; c2++) o += rpb[c2 * 40];

        out[(size_t)(blockBase + s2) * X + p] = o;
    }
}

extern "C" void kernel_launch(void* const* d_in, const int* in_sizes, int n_in,
                              void* d_out, int out_size)
{
    // inputs: 0:t 1:u 2:coeff 3:W1 4:b1 5:W2 6:b2 7:W3 8:b3
    const float* u     = (const float*)d_in[1];
    const float* coeff = (const float*)d_in[2];
    const float* W1    = (const float*)d_in[3];
    const float* b1    = (const float*)d_in[4];
    const float* W2    = (const float*)d_in[5];
    const float* b2    = (const float*)d_in[6];
    const float* W3    = (const float*)d_in[7];
    const float* b3    = (const float*)d_in[8];
    float* out = (float*)d_out;

    const int smem_bytes = SMEM_FLOATS * (int)sizeof(float);
    cudaFuncSetAttribute(l96_kernel, cudaFuncAttributeMaxDynamicSharedMemorySize, smem_bytes);

    const int n_batch = in_sizes[1] / X;           // 65536
    l96_kernel<<<n_batch / S_PER_BLK, NT, smem_bytes>>>(u, coeff, W1, b1, W2, b2, W3, b3, out);
}

// round 2
// speedup vs baseline: 1.1466x; 1.1466x over previous
#include <cuda_runtime.h>

// Lorenz96 correction with packed fp32x2 FMA (2 samples per lane-pair).
// conv1(1->72,k5,wrap)+gate -> 48ch, conv2(48->37,k5,wrap), conv3(1x1) + stencil head.

#define NT   160
#define SP   8          // samples per block
#define NPR  4          // sample pairs per block
#define X    40

#define US_STRIDE 90            // words per pair-row of u (44 cols * 2 + 2 pad)
#define H_CI      88            // words per (pair, channel) row: 44 cols * 2
#define H_PR      (48*H_CI + 2) // 4226 words per pair (+2 pad: bank de-phase)
#define PART_STR  80            // partial region stride per (pr, co)

#define OFF_COEFF 0
#define OFF_W1D   20                      // duplicated pairs: 720
#define OFF_B1D   (OFF_W1D + 720)        // duplicated pairs: 144
#define OFF_W2    (OFF_B1D + 144)        // [ (ci*5+d)*37 + co ] : 8880
#define OFF_B2    (OFF_W2 + 8880)        // 40
#define OFF_W3    (OFF_B2 + 40)          // 40
#define OFF_B3    (OFF_W3 + 40)          // 4
#define OFF_US    (OFF_B3 + 4)           // 4*90 = 360
#define OFF_HS    (OFF_US + 360)         // 4*4226 = 16904
#define SMEM_FLOATS (OFF_HS + NPR*H_PR)  // 27112 floats = 108448 B

typedef unsigned long long ull;

__device__ __forceinline__ ull ffma2(ull a, ull b, ull c) {
    ull d;
    asm("fma.rn.f32x2 %0, %1, %2, %3;" : "=l"(d) : "l"(a), "l"(b), "l"(c));
    return d;
}
__device__ __forceinline__ ull pack2(float lo, float hi) {
    ull r;
    asm("mov.b64 %0, {%1, %2};" : "=l"(r) : "f"(lo), "f"(hi));
    return r;
}
__device__ __forceinline__ void unpack2(ull v, float& lo, float& hi) {
    asm("mov.b64 {%0, %1}, %2;" : "=f"(lo), "=f"(hi) : "l"(v));
}

__global__ __launch_bounds__(NT, 2)
void l96_kernel(const float* __restrict__ u,  const float* __restrict__ coeff,
                const float* __restrict__ W1, const float* __restrict__ b1,
                const float* __restrict__ W2, const float* __restrict__ b2,
                const float* __restrict__ W3, const float* __restrict__ b3,
                float* __restrict__ out)
{
    extern __shared__ float sm[];
    float* coeffs = sm + OFF_COEFF;
    float* W1d    = sm + OFF_W1D;   // weight pairs (w,w)
    float* b1d    = sm + OFF_B1D;
    float* W2s    = sm + OFF_W2;
    float* b2s    = sm + OFF_B2;
    float* W3s    = sm + OFF_W3;
    float* b3s    = sm + OFF_B3;
    float* us     = sm + OFF_US;    // [pr][44 cols][2 lanes]
    float* hs     = sm + OFF_HS;    // [pr][48][44 cols][2 lanes]

    const int tid = threadIdx.x;
    const int blockBase = blockIdx.x * SP;

    // ---- stage weights ----
    for (int i = tid; i < 18;  i += NT) coeffs[i] = coeff[i];
    for (int i = tid; i < 360; i += NT) { float w = W1[i]; W1d[2*i] = w; W1d[2*i+1] = w; }
    for (int i = tid; i < 72;  i += NT) { float v = b1[i]; b1d[2*i] = v; b1d[2*i+1] = v; }
    for (int i = tid; i < 8880; i += NT) {
        int co = i / 240, r = i % 240;
        W2s[r * 37 + co] = W2[i];
    }
    for (int i = tid; i < 37; i += NT) { b2s[i] = b2[i]; W3s[i] = W3[i]; }
    if (tid == 0) b3s[0] = b3[0];

    // ---- stage u, interleaved sample pairs with wrap halo ----
    for (int i = tid; i < SP * X; i += NT) {
        int s = i / X, p = i % X;
        int pr = s >> 1, lane = s & 1;
        float v = u[(size_t)(blockBase + s) * X + p];
        float* ur = us + pr * US_STRIDE + lane;
        ur[(p + 2) * 2] = v;
        if (p < 2)   ur[(p + 42) * 2] = v;
        if (p >= 38) ur[(p - 38) * 2] = v;
    }
    __syncthreads();

    // ---- conv1 + relu + gate -> hs (packed pairs) ----
    for (int i = tid; i < NPR * 48 * X; i += NT) {
        int p  = i % X;
        int c  = (i / X) % 48;
        int pr = i / (X * 48);
        const ull* up = reinterpret_cast<const ull*>(us + pr * US_STRIDE);
        const ull* w1p = reinterpret_cast<const ull*>(W1d);
        const ull* b1p = reinterpret_cast<const ull*>(b1d);

        ull a = b1p[c];
        #pragma unroll
        for (int d = 0; d < 5; d++) a = ffma2(w1p[c*5 + d], up[p + d], a);
        float a0, a1; unpack2(a, a0, a1);
        a0 = fmaxf(a0, 0.f); a1 = fmaxf(a1, 0.f);
        if (c >= 24) {
            int c2 = c + 24;
            ull g = b1p[c2];
            #pragma unroll
            for (int d = 0; d < 5; d++) g = ffma2(w1p[c2*5 + d], up[p + d], g);
            float g0, g1; unpack2(g, g0, g1);
            a0 *= fmaxf(g0, 0.f); a1 *= fmaxf(g1, 0.f);
        }
        float* hr = hs + pr * H_PR + c * H_CI;
        *reinterpret_cast<float2*>(hr + 2*(p + 2)) = make_float2(a0, a1);
        if (p < 2)   *reinterpret_cast<float2*>(hr + 2*(p + 42)) = make_float2(a0, a1);
        if (p >= 38) *reinterpret_cast<float2*>(hr + 2*(p - 38)) = make_float2(a0, a1);
    }
    __syncthreads();

    // ---- conv2: thread = (pair, co); 40 packed position accumulators ----
    const int pr = tid / X;        // 0..3
    const int co = tid % X;        // active if < 37
    const bool active = (co < 37);

    ull acc[40];
    float wc = 0.f;
    if (active) {
        ull bp = pack2(b2s[co], b2s[co]);
        #pragma unroll
        for (int j = 0; j < 40; j++) acc[j] = bp;

        const float* wbase = W2s + co;
        const ull* hb = reinterpret_cast<const ull*>(hs + pr * H_PR);
        #pragma unroll 1
        for (int ci = 0; ci < 48; ci++) {
            const ull* hp = hb + ci * (H_CI/2);
            const float* w = wbase + ci * 185;
            ull w0 = pack2(w[0],   w[0]);
            ull w1 = pack2(w[37],  w[37]);
            ull w2 = pack2(w[74],  w[74]);
            ull w3_ = pack2(w[111], w[111]);
            ull w4 = pack2(w[148], w[148]);
            ull h0 = hp[0], h1 = hp[1], h2 = hp[2], h3 = hp[3];
            #pragma unroll
            for (int j = 0; j < 40; j++) {
                ull h4 = hp[j + 4];
                ull t = ffma2(w0, h0,
                        ffma2(w1, h1,
                        ffma2(w2, h2,
                        ffma2(w3_, h3,
                        ffma2(w4, h4, acc[j])))));
                acc[j] = t;
                h0 = h1; h1 = h2; h2 = h3; h3 = h4;
            }
        }
        wc = W3s[co];
    }
    __syncthreads();   // all hs reads done; safe to reuse hs for partials

    if (active) {
        float* rp = hs + (pr * 37 + co) * PART_STR;
        #pragma unroll
        for (int j = 0; j < 40; j++) {
            float a0, a1; unpack2(acc[j], a0, a1);
            a0 = wc * fmaxf(a0, 0.f);
            a1 = wc * fmaxf(a1, 0.f);
            *reinterpret_cast<float2*>(rp + 2*j) = make_float2(a0, a1);
        }
    }
    __syncthreads();

    // ---- epilogue: stencil head + b3 + sum over co ----
    for (int t = tid; t < SP * X; t += NT) {
        int s = t / X, p = t % X;
        int pr2 = s >> 1, lane = s & 1;
        const float* ur = us + pr2 * US_STRIDE + lane;
        float um2 = ur[(p+0)*2], um1 = ur[(p+1)*2], uc = ur[(p+2)*2];
        float up1 = ur[(p+3)*2], up2 = ur[(p+4)*2];
        float o = coeffs[0];
        o = fmaf(coeffs[1],  um2,       o);
        o = fmaf(coeffs[2],  um1,       o);
        o = fmaf(coeffs[3],  uc,        o);
        o = fmaf(coeffs[4],  up1,       o);
        o = fmaf(coeffs[5],  up2,       o);
        o = fmaf(coeffs[6],  um2 * um2, o);
        o = fmaf(coeffs[7],  um1 * um1, o);
        o = fmaf(coeffs[8],  uc  * uc,  o);
        o = fmaf(coeffs[9],  up1 * up1, o);
        o = fmaf(coeffs[10], up2 * up2, o);
        o = fmaf(coeffs[11], um2 * um1, o);
        o = fmaf(coeffs[12], um1 * uc,  o);
        o = fmaf(coeffs[13], uc  * up1, o);
        o = fmaf(coeffs[14], up1 * up2, o);
        o = fmaf(coeffs[15], um2 * uc,  o);
        o = fmaf(coeffs[16], um1 * up1, o);
        o = fmaf(coeffs[17], uc  * up2, o);
        o += b3s[0];

        const float* rpb = hs + pr2 * 37 * PART_STR + 2*p + lane;
        #pragma unroll 1
        for (int c = 0; c < 37; c++) o += rpb[c * PART_STR];

        out[(size_t)(blockBase + s) * X + p] = o;
    }
}

extern "C" void kernel_launch(void* const* d_in, const int* in_sizes, int n_in,
                              void* d_out, int out_size)
{
    // inputs: 0:t 1:u 2:coeff 3:W1 4:b1 5:W2 6:b2 7:W3 8:b3
    const float* u     = (const float*)d_in[1];
    const float* coeff = (const float*)d_in[2];
    const float* W1    = (const float*)d_in[3];
    const float* b1    = (const float*)d_in[4];
    const float* W2    = (const float*)d_in[5];
    const float* b2    = (const float*)d_in[6];
    const float* W3    = (const float*)d_in[7];
    const float* b3    = (const float*)d_in[8];
    float* out = (float*)d_out;

    const int smem_bytes = SMEM_FLOATS * (int)sizeof(float);
    cudaFuncSetAttribute(l96_kernel, cudaFuncAttributeMaxDynamicSharedMemorySize, smem_bytes);

    const int n_batch = in_sizes[1] / X;   // 65536
    l96_kernel<<<n_batch / SP, NT, smem_bytes>>>(u, coeff, W1, b1, W2, b2, W3, b3, out);
}

// round 4
// speedup vs baseline: 2.7219x; 2.3738x over previous
#include <cuda_runtime.h>
#include <cuda_fp16.h>
#include <cstdint>

// Lorenz96 correction via HMMA (mma.sync m16n8k16 f16->f32).
// conv1(1->72,k5,wrap)+gate in fp32 -> h fp16 (halo 44) in SMEM.
// conv2 as GEMM: D[48pad(37)][160] = W2[48][240] x im2col(h)[240][160],
// im2col folded into B-fragment addressing. Epilogue relu*W3 + reduce + stencil.

#define NT     384
#define GRID   296
#define X      40
#define SPT    4
#define NTILES 16384          // 65536 / SPT
#define AST    264            // W2h row stride (halves)
#define HST    46             // h row stride (halves)
#define HS_SAMP (48*HST)      // 2208 halves per sample

// smem byte offsets
#define SM_W2H   0            // 48*264 halves = 25344 B
#define SM_H     25344        // 4*2208 halves = 17664 B
#define SM_US    43008        // 4*44 fp32 = 704 B
#define SM_W1    43712        // 360 fp32
#define SM_B1    45152        // 72 fp32
#define SM_B2    45440        // 48 fp32 (pad 0)
#define SM_W3    45632        // 48 fp32 (pad 0)
#define SM_COEFF 45824        // 18 fp32
#define SM_B3    45896        // 1 fp32
#define SM_PART  45952        // 3*4*40 fp32 = 1920 B
#define SM_TOTAL 48000

__device__ __forceinline__ uint32_t smem_u32(const void* p) {
    uint32_t a;
    asm("{ .reg .u64 t; cvta.to.shared.u64 t, %1; cvt.u32.u64 %0, t; }" : "=r"(a) : "l"(p));
    return a;
}

__device__ __forceinline__ void ldmatrix_x4(uint32_t& a0, uint32_t& a1, uint32_t& a2, uint32_t& a3,
                                            uint32_t addr) {
    asm volatile("ldmatrix.sync.aligned.m8n8.x4.shared.b16 {%0,%1,%2,%3}, [%4];"
                 : "=r"(a0), "=r"(a1), "=r"(a2), "=r"(a3) : "r"(addr));
}

__device__ __forceinline__ void mma16816(float* c, uint32_t a0, uint32_t a1, uint32_t a2, uint32_t a3,
                                         uint32_t b0, uint32_t b1) {
    asm volatile("mma.sync.aligned.m16n8k16.row.col.f32.f16.f16.f32 "
                 "{%0,%1,%2,%3}, {%4,%5,%6,%7}, {%8,%9}, {%0,%1,%2,%3};"
                 : "+f"(c[0]), "+f"(c[1]), "+f"(c[2]), "+f"(c[3])
                 : "r"(a0), "r"(a1), "r"(a2), "r"(a3), "r"(b0), "r"(b1));
}

__device__ __forceinline__ uint32_t lds_u16(uint32_t addr) {
    uint32_t v;
    asm volatile("ld.shared.u16 %0, [%1];" : "=r"(v) : "r"(addr));
    return v;
}

__global__ __launch_bounds__(NT, 2)
void l96_hmma_kernel(const float* __restrict__ u,  const float* __restrict__ coeff,
                     const float* __restrict__ W1, const float* __restrict__ b1,
                     const float* __restrict__ W2, const float* __restrict__ b2,
                     const float* __restrict__ W3, const float* __restrict__ b3,
                     float* __restrict__ out)
{
    extern __shared__ char sm[];
    const uint32_t smb = smem_u32(sm);
    const int tid  = threadIdx.x;
    const int wid  = tid >> 5;
    const int lane = tid & 31;

    float* W1s  = (float*)(sm + SM_W1);
    float* b1s  = (float*)(sm + SM_B1);
    float* b2s  = (float*)(sm + SM_B2);
    float* w3s  = (float*)(sm + SM_W3);
    float* usf  = (float*)(sm + SM_US);
    float* part = (float*)(sm + SM_PART);   // [m][s][40]
    __half* W2h = (__half*)(sm + SM_W2H);
    __half* hsh = (__half*)(sm + SM_H);

    // ---- stage weights ----
    for (int i = tid; i < 6336; i += NT) ((uint32_t*)(sm + SM_W2H))[i] = 0;  // zero W2h
    for (int i = tid; i < 360; i += NT) W1s[i] = W1[i];
    for (int i = tid; i < 72;  i += NT) b1s[i] = b1[i];
    for (int i = tid; i < 48;  i += NT) {
        b2s[i] = (i < 37) ? b2[i] : 0.f;
        w3s[i] = (i < 37) ? W3[i] : 0.f;
    }
    for (int i = tid; i < 18; i += NT) ((float*)(sm + SM_COEFF))[i] = coeff[i];
    if (tid == 0) ((float*)(sm + SM_B3))[0] = b3[0];
    __syncthreads();
    for (int i = tid; i < 37 * 240; i += NT) {
        int co = i / 240, k = i % 240;
        W2h[co * AST + k] = __float2half(W2[i]);
    }
    __syncthreads();

    // warp roles for the GEMM
    const int mw = wid >> 2;   // 0..2  (M-tile: rows mw*16 .. +15)
    const int sw = wid & 3;    // 0..3  (sample within tile)

    // ldmatrix A address (per-thread row), col offset k0*2 added in loop
    const uint32_t a_addr0 = smb + SM_W2H +
        (uint32_t)(((mw * 16 + (lane & 15)) * AST + ((lane >> 4) << 3)) * 2);
    // B base: sample + column (n = lane>>2)
    const uint32_t h_s = smb + SM_H + (uint32_t)(sw * HS_SAMP * 2);
    const uint32_t b_col = h_s + (uint32_t)((lane >> 2) << 1);

    for (int tile = blockIdx.x; tile < NTILES; tile += GRID) {
        const size_t gbase = (size_t)tile * (SPT * X);

        // ---- stage u (4 samples, halo 44) ----
        if (tid < SPT * X) {
            int s = tid / X, p = tid % X;
            float v = u[gbase + tid];
            float* ur = usf + s * 44;
            ur[p + 2] = v;
            if (p < 2)   ur[p + 42] = v;
            if (p >= 38) ur[p - 38] = v;
        }
        __syncthreads();

        // ---- conv1 + gate (fp32) -> h fp16 halo ----
        for (int i = tid; i < SPT * 48 * X; i += NT) {
            int p = i % X;
            int c = (i / X) % 48;
            int s = i / (48 * X);
            const float* ur = usf + s * 44 + p;
            float a = b1s[c];
            #pragma unroll
            for (int d = 0; d < 5; d++) a = fmaf(W1s[c * 5 + d], ur[d], a);
            a = fmaxf(a, 0.f);
            if (c >= 24) {
                int c2 = c + 24;
                float g = b1s[c2];
                #pragma unroll
                for (int d = 0; d < 5; d++) g = fmaf(W1s[c2 * 5 + d], ur[d], g);
                a *= fmaxf(g, 0.f);
            }
            __half hv = __float2half(a);
            __half* hr = hsh + s * HS_SAMP + c * HST;
            hr[p + 2] = hv;
            if (p < 2)   hr[p + 42] = hv;
            if (p >= 38) hr[p - 38] = hv;
        }
        __syncthreads();

        // ---- GEMM: 15 k-tiles x 5 n-tiles of m16n8k16 ----
        float acc[20];
        #pragma unroll
        for (int j = 0; j < 20; j++) acc[j] = 0.f;

        #pragma unroll
        for (int kt = 0; kt < 15; kt++) {
            const int k0 = kt * 16;
            uint32_t a0, a1, a2, a3;
            ldmatrix_x4(a0, a1, a2, a3, a_addr0 + (uint32_t)(k0 * 2));

            // B row byte-offsets for this thread's 4 k values (im2col fold)
            const int kk = k0 + ((lane & 3) << 1);
            const int k2 = kk + 1, k3 = kk + 8, k4 = kk + 9;
            const uint32_t o1 = (uint32_t)(((kk / 5) * HST + (kk % 5)) * 2);
            const uint32_t o2 = (uint32_t)(((k2 / 5) * HST + (k2 % 5)) * 2);
            const uint32_t o3 = (uint32_t)(((k3 / 5) * HST + (k3 % 5)) * 2);
            const uint32_t o4 = (uint32_t)(((k4 / 5) * HST + (k4 % 5)) * 2);

            #pragma unroll
            for (int nt = 0; nt < 5; nt++) {
                const uint32_t cb = b_col + (uint32_t)(nt * 16);
                uint32_t lo0 = lds_u16(cb + o1);
                uint32_t hi0 = lds_u16(cb + o2);
                uint32_t lo1 = lds_u16(cb + o3);
                uint32_t hi1 = lds_u16(cb + o4);
                uint32_t bf0 = lo0 | (hi0 << 16);
                uint32_t bf1 = lo1 | (hi1 << 16);
                mma16816(acc + nt * 4, a0, a1, a2, a3, bf0, bf1);
            }
        }

        // ---- epilogue: relu(acc+b2)*W3, reduce over 16 rows, store partials ----
        {
            const int r0 = mw * 16 + (lane >> 2);
            const float b2a = b2s[r0],     w3a = w3s[r0];
            const float b2b = b2s[r0 + 8], w3b = w3s[r0 + 8];
            float* pp = part + (mw * 4 + sw) * 40;
            #pragma unroll
            for (int nt = 0; nt < 5; nt++) {
                float t0 = fmaxf(acc[nt*4+0] + b2a, 0.f) * w3a
                         + fmaxf(acc[nt*4+2] + b2b, 0.f) * w3b;
                float t1 = fmaxf(acc[nt*4+1] + b2a, 0.f) * w3a
                         + fmaxf(acc[nt*4+3] + b2b, 0.f) * w3b;
                #pragma unroll
                for (int ofs = 4; ofs <= 16; ofs <<= 1) {
                    t0 += __shfl_xor_sync(0xFFFFFFFF, t0, ofs);
                    t1 += __shfl_xor_sync(0xFFFFFFFF, t1, ofs);
                }
                if (lane < 4) {
                    pp[nt * 8 + lane * 2]     = t0;
                    pp[nt * 8 + lane * 2 + 1] = t1;
                }
            }
        }
        __syncthreads();

        // ---- final: stencil head + b3 + sum of 3 m-partials ----
        if (tid < SPT * X) {
            int s = tid / X, p = tid % X;
            const float* ur = usf + s * 44 + p;
            const float* cf = (const float*)(sm + SM_COEFF);
            float um2 = ur[0], um1 = ur[1], uc = ur[2], up1 = ur[3], up2 = ur[4];
            float o = cf[0];
            o = fmaf(cf[1],  um2,       o);
            o = fmaf(cf[2],  um1,       o);
            o = fmaf(cf[3],  uc,        o);
            o = fmaf(cf[4],  up1,       o);
            o = fmaf(cf[5],  up2,       o);
            o = fmaf(cf[6],  um2 * um2, o);
            o = fmaf(cf[7],  um1 * um1, o);
            o = fmaf(cf[8],  uc  * uc,  o);
            o = fmaf(cf[9],  up1 * up1, o);
            o = fmaf(cf[10], up2 * up2, o);
            o = fmaf(cf[11], um2 * um1, o);
            o = fmaf(cf[12], um1 * uc,  o);
            o = fmaf(cf[13], uc  * up1, o);
            o = fmaf(cf[14], up1 * up2, o);
            o = fmaf(cf[15], um2 * uc,  o);
            o = fmaf(cf[16], um1 * up1, o);
            o = fmaf(cf[17], uc  * up2, o);
            o += ((float*)(sm + SM_B3))[0];
            o += part[(0 * 4 + s) * 40 + p];
            o += part[(1 * 4 + s) * 40 + p];
            o += part[(2 * 4 + s) * 40 + p];
            out[gbase + tid] = o;
        }
        __syncthreads();
    }
}

extern "C" void kernel_launch(void* const* d_in, const int* in_sizes, int n_in,
                              void* d_out, int out_size)
{
    // inputs: 0:t 1:u 2:coeff 3:W1 4:b1 5:W2 6:b2 7:W3 8:b3
    const float* u     = (const float*)d_in[1];
    const float* coeff = (const float*)d_in[2];
    const float* W1    = (const float*)d_in[3];
    const float* b1    = (const float*)d_in[4];
    const float* W2    = (const float*)d_in[5];
    const float* b2    = (const float*)d_in[6];
    const float* W3    = (const float*)d_in[7];
    const float* b3    = (const float*)d_in[8];
    float* out = (float*)d_out;

    cudaFuncSetAttribute(l96_hmma_kernel, cudaFuncAttributeMaxDynamicSharedMemorySize, SM_TOTAL);
    l96_hmma_kernel<<<GRID, NT, SM_TOTAL>>>(u, coeff, W1, b1, W2, b2, W3, b3, out);
}

// round 6
// speedup vs baseline: 6.3984x; 2.3507x over previous
#include <cuda_runtime.h>
#include <cuda_fp16.h>
#include <cstdint>

// Lorenz96 correction via HMMA, K reordered to d*48+ci so B frags come
// straight from transposed conv1 output via ldmatrix (no scalar im2col).
// conv1(1->72,k5,wrap)+gate fp32 -> hT[44][48] fp16 per sample.
// conv2 GEMM: D[48pad(37)][160] = W2perm[48][240] x B[240][160].
// Epilogue relu(+b2)*W3, row-reduce, + fp32 stencil head.
// FIX vs R5: B halo row is n + d (not n + 4 - d).

#define NT     384
#define GRID   296
#define X      40
#define SPT    4
#define NTILES 16384          // 65536 / SPT
#define AST    248            // W2h row stride (halves), 496B = 31*16
#define HTST   56             // hT row stride (halves), 112B = 7*16
#define HT_SAMP (44*HTST)     // 2464 halves per sample

// smem byte offsets (all 16B aligned)
#define SM_W2H   0            // 48*248*2 = 23808
#define SM_HT    23808        // 4*2464*2 = 19712
#define SM_US    43520        // 4*44 fp32 = 704
#define SM_W1    44224        // 360 fp32 = 1440
#define SM_B1    45664        // 72 fp32 = 288
#define SM_B2    45952        // 48 fp32 = 192
#define SM_W3    46144        // 48 fp32 = 192
#define SM_COEFF 46336        // 18 fp32 = 72
#define SM_B3    46408        // 4
#define SM_PART  46464        // 12*40 fp32 = 1920
#define SM_TOTAL 48384

__device__ __forceinline__ uint32_t smem_u32(const void* p) {
    uint32_t a;
    asm("{ .reg .u64 t; cvta.to.shared.u64 t, %1; cvt.u32.u64 %0, t; }" : "=r"(a) : "l"(p));
    return a;
}
__device__ __forceinline__ void ldmatrix_x4(uint32_t& a0, uint32_t& a1, uint32_t& a2, uint32_t& a3,
                                            uint32_t addr) {
    asm volatile("ldmatrix.sync.aligned.m8n8.x4.shared.b16 {%0,%1,%2,%3}, [%4];"
                 : "=r"(a0), "=r"(a1), "=r"(a2), "=r"(a3) : "r"(addr));
}
__device__ __forceinline__ void ldmatrix_x2(uint32_t& a0, uint32_t& a1, uint32_t addr) {
    asm volatile("ldmatrix.sync.aligned.m8n8.x2.shared.b16 {%0,%1}, [%2];"
                 : "=r"(a0), "=r"(a1) : "r"(addr));
}
__device__ __forceinline__ void mma16816(float* c, uint32_t a0, uint32_t a1, uint32_t a2, uint32_t a3,
                                         uint32_t b0, uint32_t b1) {
    asm volatile("mma.sync.aligned.m16n8k16.row.col.f32.f16.f16.f32 "
                 "{%0,%1,%2,%3}, {%4,%5,%6,%7}, {%8,%9}, {%0,%1,%2,%3};"
                 : "+f"(c[0]), "+f"(c[1]), "+f"(c[2]), "+f"(c[3])
                 : "r"(a0), "r"(a1), "r"(a2), "r"(a3), "r"(b0), "r"(b1));
}

__global__ __launch_bounds__(NT, 2)
void l96_hmma2_kernel(const float* __restrict__ u,  const float* __restrict__ coeff,
                      const float* __restrict__ W1, const float* __restrict__ b1,
                      const float* __restrict__ W2, const float* __restrict__ b2,
                      const float* __restrict__ W3, const float* __restrict__ b3,
                      float* __restrict__ out)
{
    extern __shared__ char sm[];
    const uint32_t smb = smem_u32(sm);
    const int tid  = threadIdx.x;
    const int wid  = tid >> 5;
    const int lane = tid & 31;

    float* W1s  = (float*)(sm + SM_W1);
    float* b1s  = (float*)(sm + SM_B1);
    float* b2s  = (float*)(sm + SM_B2);
    float* w3s  = (float*)(sm + SM_W3);
    float* usf  = (float*)(sm + SM_US);
    float* part = (float*)(sm + SM_PART);   // [mw*4+sw][40]
    __half* W2h = (__half*)(sm + SM_W2H);
    __half* hTh = (__half*)(sm + SM_HT);

    // ---- stage weights ----
    for (int i = tid; i < 48 * AST / 2; i += NT) ((uint32_t*)(sm + SM_W2H))[i] = 0;
    for (int i = tid; i < 360; i += NT) W1s[i] = W1[i];
    for (int i = tid; i < 72;  i += NT) b1s[i] = b1[i];
    for (int i = tid; i < 48;  i += NT) {
        b2s[i] = (i < 37) ? b2[i] : 0.f;
        w3s[i] = (i < 37) ? W3[i] : 0.f;
    }
    for (int i = tid; i < 18; i += NT) ((float*)(sm + SM_COEFF))[i] = coeff[i];
    if (tid == 0) ((float*)(sm + SM_B3))[0] = b3[0];
    __syncthreads();
    // W2 with permuted K: W2h[co][d*48+ci] = W2[co][ci*5+d]
    for (int i = tid; i < 37 * 240; i += NT) {
        int co = i / 240, k = i % 240;
        int ci = k / 5, d = k % 5;
        W2h[co * AST + d * 48 + ci] = __float2half(W2[i]);
    }
    __syncthreads();

    // warp roles
    const int mw = wid >> 2;   // 0..2  M-tile (rows mw*16..+15)
    const int sw = wid & 3;    // 0..3  sample

    // A ldmatrix lane address (k0 byte offset added per kt)
    const uint32_t a_lane = smb + SM_W2H +
        (uint32_t)(((mw * 16 + (lane & 15)) * AST + ((lane >> 4) << 3)) * 2);
    // B lane addresses into hT (halo row = n + d, cols ci0 + ci_off)
    const uint32_t hT_s = smb + SM_HT + (uint32_t)(sw * HT_SAMP * 2);
    const uint32_t b_lane4 = hT_s +
        (uint32_t)((((lane & 7) + ((lane >> 4) & 1) * 8) * HTST + ((lane >> 3) & 1) * 8) * 2);
    const uint32_t b_lane2 = hT_s +
        (uint32_t)(((lane & 7) * HTST + ((lane >> 3) & 1) * 8) * 2);

    // conv1 role: c fixed per thread, (s,p) strided
    const int c1c  = tid % 48;
    const int sp0  = tid / 48;          // 0..7
    float w1r[5], w1g[5];
    float b1v, b1g;
    {
        b1v = b1s[c1c];
        #pragma unroll
        for (int d = 0; d < 5; d++) w1r[d] = W1s[c1c * 5 + d];
        if (c1c >= 24) {
            int c2 = c1c + 24;
            b1g = b1s[c2];
            #pragma unroll
            for (int d = 0; d < 5; d++) w1g[d] = W1s[c2 * 5 + d];
        }
    }

    for (int tile = blockIdx.x; tile < NTILES; tile += GRID) {
        const size_t gbase = (size_t)tile * (SPT * X);

        // ---- stage u (4 samples, halo 44) ----
        if (tid < SPT * X) {
            int s = tid / X, p = tid % X;
            float v = u[gbase + tid];
            float* ur = usf + s * 44;
            ur[p + 2] = v;
            if (p < 2)   ur[p + 42] = v;
            if (p >= 38) ur[p - 38] = v;
        }
        __syncthreads();

        // ---- conv1 + gate -> hT fp16 (transposed, c contiguous) ----
        #pragma unroll
        for (int j = 0; j < 20; j++) {
            int sp = sp0 + j * 8;       // 0..159
            int s = sp / X, p = sp % X;
            const float* ur = usf + s * 44 + p;
            float u0 = ur[0], u1 = ur[1], u2 = ur[2], u3 = ur[3], u4 = ur[4];
            float a = b1v;
            a = fmaf(w1r[0], u0, a); a = fmaf(w1r[1], u1, a); a = fmaf(w1r[2], u2, a);
            a = fmaf(w1r[3], u3, a); a = fmaf(w1r[4], u4, a);
            a = fmaxf(a, 0.f);
            if (c1c >= 24) {
                float g = b1g;
                g = fmaf(w1g[0], u0, g); g = fmaf(w1g[1], u1, g); g = fmaf(w1g[2], u2, g);
                g = fmaf(w1g[3], u3, g); g = fmaf(w1g[4], u4, g);
                a *= fmaxf(g, 0.f);
            }
            __half hv = __float2half(a);
            __half* ht = hTh + s * HT_SAMP;
            ht[(p + 2) * HTST + c1c] = hv;
            if (p < 2)   ht[(p + 42) * HTST + c1c] = hv;
            if (p >= 38) ht[(p - 38) * HTST + c1c] = hv;
        }
        __syncthreads();

        // ---- GEMM: 15 kt, per kt: A x4 + B 2*x4 + x2, 5 HMMA ----
        float acc[20];
        #pragma unroll
        for (int j = 0; j < 20; j++) acc[j] = 0.f;

        #pragma unroll
        for (int kt = 0; kt < 15; kt++) {
            const int d   = kt / 3;
            const int ci0 = (kt % 3) * 16;
            uint32_t a0, a1, a2, a3;
            ldmatrix_x4(a0, a1, a2, a3, a_lane + (uint32_t)(kt * 32));

            const uint32_t bofs = (uint32_t)(((d * HTST) + ci0) * 2);   // halo row n + d
            uint32_t b0, b1_, b2_, b3_;
            ldmatrix_x4(b0, b1_, b2_, b3_, b_lane4 + bofs);                       // n 0..15
            mma16816(acc + 0, a0, a1, a2, a3, b0, b1_);
            mma16816(acc + 4, a0, a1, a2, a3, b2_, b3_);
            ldmatrix_x4(b0, b1_, b2_, b3_, b_lane4 + bofs + (uint32_t)(16 * HTST * 2)); // n 16..31
            mma16816(acc + 8,  a0, a1, a2, a3, b0, b1_);
            mma16816(acc + 12, a0, a1, a2, a3, b2_, b3_);
            uint32_t c0, c1;
            ldmatrix_x2(c0, c1, b_lane2 + bofs + (uint32_t)(32 * HTST * 2));           // n 32..39
            mma16816(acc + 16, a0, a1, a2, a3, c0, c1);
        }

        // ---- epilogue: relu(acc+b2)*W3, reduce over 16 rows ----
        {
            const int r0 = mw * 16 + (lane >> 2);
            const float b2a = b2s[r0],     w3a = w3s[r0];
            const float b2b = b2s[r0 + 8], w3b = w3s[r0 + 8];
            float* pp = part + (mw * 4 + sw) * 40;
            #pragma unroll
            for (int nt = 0; nt < 5; nt++) {
                float t0 = fmaxf(acc[nt*4+0] + b2a, 0.f) * w3a
                         + fmaxf(acc[nt*4+2] + b2b, 0.f) * w3b;
                float t1 = fmaxf(acc[nt*4+1] + b2a, 0.f) * w3a
                         + fmaxf(acc[nt*4+3] + b2b, 0.f) * w3b;
                #pragma unroll
                for (int ofs = 4; ofs <= 16; ofs <<= 1) {
                    t0 += __shfl_xor_sync(0xFFFFFFFF, t0, ofs);
                    t1 += __shfl_xor_sync(0xFFFFFFFF, t1, ofs);
                }
                if (lane < 4) {
                    pp[nt * 8 + lane * 2]     = t0;
                    pp[nt * 8 + lane * 2 + 1] = t1;
                }
            }
        }
        __syncthreads();

        // ---- final: stencil head + b3 + sum of 3 m-partials ----
        if (tid < SPT * X) {
            int s = tid / X, p = tid % X;
            const float* ur = usf + s * 44 + p;
            const float* cf = (const float*)(sm + SM_COEFF);
            float um2 = ur[0], um1 = ur[1], uc = ur[2], up1 = ur[3], up2 = ur[4];
            float o = cf[0];
            o = fmaf(cf[1],  um2,       o);
            o = fmaf(cf[2],  um1,       o);
            o = fmaf(cf[3],  uc,        o);
            o = fmaf(cf[4],  up1,       o);
            o = fmaf(cf[5],  up2,       o);
            o = fmaf(cf[6],  um2 * um2, o);
            o = fmaf(cf[7],  um1 * um1, o);
            o = fmaf(cf[8],  uc  * uc,  o);
            o = fmaf(cf[9],  up1 * up1, o);
            o = fmaf(cf[10], up2 * up2, o);
            o = fmaf(cf[11], um2 * um1, o);
            o = fmaf(cf[12], um1 * uc,  o);
            o = fmaf(cf[13], uc  * up1, o);
            o = fmaf(cf[14], up1 * up2, o);
            o = fmaf(cf[15], um2 * uc,  o);
            o = fmaf(cf[16], um1 * up1, o);
            o = fmaf(cf[17], uc  * up2, o);
            o += ((float*)(sm + SM_B3))[0];
            o += part[(0 * 4 + s) * 40 + p];
            o += part[(1 * 4 + s) * 40 + p];
            o += part[(2 * 4 + s) * 40 + p];
            out[gbase + tid] = o;
        }
        __syncthreads();
    }
}

extern "C" void kernel_launch(void* const* d_in, const int* in_sizes, int n_in,
                              void* d_out, int out_size)
{
    // inputs: 0:t 1:u 2:coeff 3:W1 4:b1 5:W2 6:b2 7:W3 8:b3
    const float* u     = (const float*)d_in[1];
    const float* coeff = (const float*)d_in[2];
    const float* W1    = (const float*)d_in[3];
    const float* b1    = (const float*)d_in[4];
    const float* W2    = (const float*)d_in[5];
    const float* b2    = (const float*)d_in[6];
    const float* W3    = (const float*)d_in[7];
    const float* b3    = (const float*)d_in[8];
    float* out = (float*)d_out;

    cudaFuncSetAttribute(l96_hmma2_kernel, cudaFuncAttributeMaxDynamicSharedMemorySize, SM_TOTAL);
    l96_hmma2_kernel<<<GRID, NT, SM_TOTAL>>>(u, coeff, W1, b1, W2, b2, W3, b3, out);
}